// round 1
// baseline (speedup 1.0000x reference)
#include <cuda_runtime.h>
#include <math.h>

#define T_ 256
#define B_ 16
#define E_ 512
#define H_ 2048
#define N_ 14839
#define U_ 48
#define G4H (4*H_)          /* 8192 */
#define EPS_ 1e-6f

/* ---------------- scratch (static __device__, no allocation) ---------------- */
__device__ float g_xh_m[T_*B_*E_];        // (T,B,E)
__device__ float g_xh_c[T_*B_*E_];
__device__ float g_emb[U_*B_*E_];         // gathered embeddings (U*B, E)
__device__ float g_eg[(size_t)U_*B_*G4H]; // emb part of gates + bias, (U*B, 4H)
__device__ float g_gates[B_*G4H];
__device__ float g_h[2][B_*H_];
__device__ float g_c[2][B_*H_];
__device__ float g_ctx[2][B_*E_];
__device__ float g_alpha[2][T_*B_];
__device__ float g_sm[B_*E_];
__device__ float g_sc[B_*E_];
__device__ float g_p[T_*B_];
__device__ float g_u[T_*B_];
__device__ float g_beta[T_*B_];
__device__ float g_scall[U_*B_*2*E_];     // per-step [s ; ctx], (U*B, 2E)

/* ---------------- init ---------------- */
__global__ void init_state(float* h, float* c, float* ctx, float* alpha) {
    int i = blockIdx.x * blockDim.x + threadIdx.x;
    if (i < B_*H_) { h[i] = 0.f; c[i] = 0.f; }
    if (i < B_*E_) ctx[i] = 0.f;
    if (i < T_*B_) alpha[i] = (i < B_) ? 1.f : 0.f;   // alpha[t*B+b], t==0 -> 1
}

/* ---------------- embedding gather ---------------- */
__global__ void gather_emb(const float* __restrict__ emb_table,
                           const int* __restrict__ label,
                           float* __restrict__ emb) {
    int r = blockIdx.x;                    // r = u*B + b  (label is (U,B) row-major)
    int n = label[r];
    const float* src = emb_table + (size_t)n * E_;
    float* dst = emb + (size_t)r * E_;
    for (int i = threadIdx.x; i < E_; i += blockDim.x) dst[i] = src[i];
}

/* ---------------- big GEMM: C[m, j] = sum_k W[m,k]*X[j,k] (+bias[m]) ----------------
   W rows: M (ldw), X rows: Nx (ldx). C index = m*ldcw + j*ldcx.                      */
#define BM 128
#define BN 128
#define BK 8
__global__ __launch_bounds__(256) void sgemm_tn(
        const float* __restrict__ W, int ldw,
        const float* __restrict__ X, int ldx,
        const float* __restrict__ bias,
        float* __restrict__ C, size_t ldcw, size_t ldcx,
        int M, int Nx, int K)
{
    __shared__ float Ws[BK][BM+4];
    __shared__ float Xs[BK][BN+4];
    int m0 = blockIdx.y * BM;
    int x0 = blockIdx.x * BN;
    int tid = threadIdx.x;
    int tx = tid & 15, ty = tid >> 4;

    float acc[8][8];
#pragma unroll
    for (int i = 0; i < 8; i++)
#pragma unroll
        for (int j = 0; j < 8; j++) acc[i][j] = 0.f;

    int lrow = tid >> 1;
    int lkq  = (tid & 1) * 4;

    for (int k0 = 0; k0 < K; k0 += BK) {
        float4 v = make_float4(0.f,0.f,0.f,0.f);
        if (m0 + lrow < M)
            v = *(const float4*)(W + (size_t)(m0 + lrow) * ldw + k0 + lkq);
        Ws[lkq+0][lrow] = v.x; Ws[lkq+1][lrow] = v.y;
        Ws[lkq+2][lrow] = v.z; Ws[lkq+3][lrow] = v.w;

        float4 u = make_float4(0.f,0.f,0.f,0.f);
        if (x0 + lrow < Nx)
            u = *(const float4*)(X + (size_t)(x0 + lrow) * ldx + k0 + lkq);
        Xs[lkq+0][lrow] = u.x; Xs[lkq+1][lrow] = u.y;
        Xs[lkq+2][lrow] = u.z; Xs[lkq+3][lrow] = u.w;
        __syncthreads();

#pragma unroll
        for (int kk = 0; kk < BK; kk++) {
            float4 w0 = *(const float4*)&Ws[kk][ty*8];
            float4 w1 = *(const float4*)&Ws[kk][ty*8+4];
            float4 x0v = *(const float4*)&Xs[kk][tx*8];
            float4 x1v = *(const float4*)&Xs[kk][tx*8+4];
            float rw[8] = {w0.x,w0.y,w0.z,w0.w,w1.x,w1.y,w1.z,w1.w};
            float rx[8] = {x0v.x,x0v.y,x0v.z,x0v.w,x1v.x,x1v.y,x1v.z,x1v.w};
#pragma unroll
            for (int i = 0; i < 8; i++)
#pragma unroll
                for (int j = 0; j < 8; j++) acc[i][j] += rw[i] * rx[j];
        }
        __syncthreads();
    }

#pragma unroll
    for (int i = 0; i < 8; i++) {
        int m = m0 + ty*8 + i;
        if (m >= M) continue;
        float bv = bias ? bias[m] : 0.f;
#pragma unroll
        for (int j = 0; j < 8; j++) {
            int xr = x0 + tx*8 + j;
            if (xr < Nx)
                C[(size_t)m * ldcw + (size_t)xr * ldcx] = acc[i][j] + bv;
        }
    }
}

/* ---------------- batch-16 GEMV: C[b,n] = (C0[b,n]) + sum_k A[b,k]*W[n,k] --------- */
__global__ __launch_bounds__(256) void gemv16(
        const float* __restrict__ A, int lda, int K,
        const float* __restrict__ W, int ldw,
        const float* __restrict__ C0, int ldc0,
        float* __restrict__ C, int ldc, int N)
{
    int warp = (blockIdx.x * blockDim.x + threadIdx.x) >> 5;
    int lane = threadIdx.x & 31;
    if (warp >= N) return;
    const float* Wr = W + (size_t)warp * ldw;
    float acc[16];
#pragma unroll
    for (int b = 0; b < 16; b++) acc[b] = 0.f;

    for (int k = lane * 4; k < K; k += 128) {
        float4 wv = *(const float4*)(Wr + k);
#pragma unroll
        for (int b = 0; b < 16; b++) {
            float4 av = *(const float4*)(A + (size_t)b * lda + k);
            acc[b] += wv.x*av.x + wv.y*av.y + wv.z*av.z + wv.w*av.w;
        }
    }
#pragma unroll
    for (int b = 0; b < 16; b++) {
#pragma unroll
        for (int off = 16; off > 0; off >>= 1)
            acc[b] += __shfl_xor_sync(0xffffffffu, acc[b], off);
    }
    if (lane < 16) {
        float r = 0.f;
#pragma unroll
        for (int b = 0; b < 16; b++) if (lane == b) r = acc[b];
        if (C0) r += C0[(size_t)lane * ldc0 + warp];
        C[(size_t)lane * ldc + warp] = r;
    }
}

/* ---------------- LSTM pointwise ---------------- */
__device__ __forceinline__ float sigm(float x) { return 1.f / (1.f + expf(-x)); }

__global__ void lstm_pointwise(const float* __restrict__ gates,
                               const float* __restrict__ c_in,
                               float* __restrict__ c_out,
                               float* __restrict__ h_out) {
    int i = blockIdx.x * blockDim.x + threadIdx.x;   // B*H
    if (i >= B_*H_) return;
    int b = i >> 11, k = i & (H_-1);
    const float* g = gates + (size_t)b * G4H;
    float gi = g[k], gf = g[H_ + k], gg = g[2*H_ + k], go = g[3*H_ + k];
    float cn = sigm(gf) * c_in[i] + sigm(gi) * tanhf(gg);
    c_out[i] = cn;
    h_out[i] = sigm(go) * tanhf(cn);
}

/* ---------------- monotonic / chunk energies ---------------- */
__global__ void energies(const float* __restrict__ sm, const float* __restrict__ sc,
                         const float* __restrict__ xm, const float* __restrict__ xc,
                         const float* __restrict__ v_m, const float* __restrict__ v_c,
                         const float* __restrict__ r_m, const float* __restrict__ att_mask,
                         float* __restrict__ p, float* __restrict__ uu)
{
    int w = (blockIdx.x * blockDim.x + threadIdx.x) >> 5;
    int lane = threadIdx.x & 31;
    if (w >= T_*B_) return;
    int t = w >> 4, b = w & 15;
    const float* xmp = xm + (size_t)(t*B_ + b) * E_;
    const float* xcp = xc + (size_t)(t*B_ + b) * E_;
    const float* smp = sm + (size_t)b * E_;
    const float* scp = sc + (size_t)b * E_;
    float am = 0.f, ac = 0.f;
    for (int e = lane * 4; e < E_; e += 128) {
        float4 a  = *(const float4*)(xmp + e);
        float4 s4 = *(const float4*)(smp + e);
        float4 v4 = *(const float4*)(v_m + e);
        am += v4.x*tanhf(a.x+s4.x) + v4.y*tanhf(a.y+s4.y)
            + v4.z*tanhf(a.z+s4.z) + v4.w*tanhf(a.w+s4.w);
        float4 a2  = *(const float4*)(xcp + e);
        float4 s42 = *(const float4*)(scp + e);
        float4 v42 = *(const float4*)(v_c + e);
        ac += v42.x*tanhf(a2.x+s42.x) + v42.y*tanhf(a2.y+s42.y)
            + v42.z*tanhf(a2.z+s42.z) + v42.w*tanhf(a2.w+s42.w);
    }
#pragma unroll
    for (int off = 16; off > 0; off >>= 1) {
        am += __shfl_xor_sync(0xffffffffu, am, off);
        ac += __shfl_xor_sync(0xffffffffu, ac, off);
    }
    if (lane == 0) {
        float mk = att_mask[b*T_ + t];
        float e_ = am + r_m[0];
        p[t*B_ + b] = sigm(e_) * mk;
        uu[t*B_ + b] = ac;
    }
}

/* ---------------- per-b scans: alpha recursion + beta ---------------- */
__device__ __forceinline__ float scan_add(float v, float* buf, int t) {
    buf[t] = v; __syncthreads();
#pragma unroll
    for (int off = 1; off < T_; off <<= 1) {
        float x = (t >= off) ? buf[t-off] : 0.f;
        __syncthreads();
        buf[t] += x;
        __syncthreads();
    }
    return buf[t];
}
__device__ __forceinline__ float scan_mul(float v, float* buf, int t) {
    buf[t] = v; __syncthreads();
#pragma unroll
    for (int off = 1; off < T_; off <<= 1) {
        float x = (t >= off) ? buf[t-off] : 1.f;
        __syncthreads();
        buf[t] *= x;
        __syncthreads();
    }
    return buf[t];
}

__global__ void scanstep(const float* __restrict__ p, const float* __restrict__ uu,
                         const float* __restrict__ alpha_in, const float* __restrict__ att_mask,
                         float* __restrict__ alpha_out, float* __restrict__ beta)
{
    __shared__ float bufA[T_], bufB[T_], bufC[T_], bufD[T_], red[T_];
    int b = blockIdx.x, t = threadIdx.x;
    float pv = p[t*B_ + b];
    float uv = uu[t*B_ + b];
    float ap = alpha_in[t*B_ + b];
    float mk = att_mask[b*T_ + t];

    red[t] = uv; __syncthreads();
    for (int off = 128; off > 0; off >>= 1) {
        if (t < off) red[t] = fmaxf(red[t], red[t+off]);
        __syncthreads();
    }
    float um = red[0];

    float eu = expf(uv - um) * mk;
    float cs = scan_add(eu, bufA, t);
    float denom = cs - (t >= 8 ? bufA[t-8] : 0.f);

    (void)scan_mul(1.f - pv, bufB, t);
    float cp = (t == 0) ? 1.f : bufB[t-1];

    float q = ap / fmaxf(cp, EPS_);
    float qs = scan_add(q, bufC, t);
    float av = pv * cp * qs;

    float rk = av / fmaxf(denom, EPS_);
    (void)scan_add(rk, bufD, t);
    int hi = (t + 7 > T_-1) ? (T_-1) : (t + 7);
    float bv = eu * (bufD[hi] - (t > 0 ? bufD[t-1] : 0.f));

    alpha_out[t*B_ + b] = av;
    beta[t*B_ + b] = bv;
}

/* ---------------- ctx = sum_t beta[t,b] * x[t,b,:] ---------------- */
__global__ void ctx_update(const float* __restrict__ beta, const float* __restrict__ x,
                           float* __restrict__ ctx_out, float* __restrict__ sc_slot)
{
    __shared__ float sb[T_];
    int b = blockIdx.x;
    for (int t = threadIdx.x; t < T_; t += blockDim.x) sb[t] = beta[t*B_ + b];
    __syncthreads();
    int d = threadIdx.x;          // blockDim = 512 = E_
    const float* xp = x + (size_t)b * E_ + d;
    float acc = 0.f;
#pragma unroll 4
    for (int t = 0; t < T_; t++) acc += sb[t] * xp[(size_t)t * B_ * E_];
    ctx_out[b*E_ + d] = acc;
    sc_slot[(size_t)b * (2*E_) + E_ + d] = acc;   // ctx half of [s;ctx]
}

/* ---------------- host launcher ---------------- */
extern "C" void kernel_launch(void* const* d_in, const int* in_sizes, int n_in,
                              void* d_out, int out_size)
{
    const float* x        = (const float*)d_in[0];
    const float* att_mask = (const float*)d_in[1];
    const float* emb_tab  = (const float*)d_in[2];
    const float* W_ih     = (const float*)d_in[3];
    const float* W_hh     = (const float*)d_in[4];
    const float* b_lstm   = (const float*)d_in[5];
    const float* W_proj   = (const float*)d_in[6];
    const float* Ws_m     = (const float*)d_in[7];
    const float* Wh_m     = (const float*)d_in[8];
    const float* v_m      = (const float*)d_in[9];
    const float* r_m      = (const float*)d_in[10];
    const float* Ws_c     = (const float*)d_in[11];
    const float* Wh_c     = (const float*)d_in[12];
    const float* v_c      = (const float*)d_in[13];
    const float* W_am     = (const float*)d_in[14];
    const float* W_lm     = (const float*)d_in[15];
    const int*   label    = (const int*)d_in[16];

    float* out_am = (float*)d_out;
    float* out_lm = out_am + (size_t)N_ * U_ * B_;

    float *xh_m, *xh_c, *emb, *eg, *gates, *hb, *cb, *ctxb, *alb, *sm, *sc, *p, *uu, *beta, *scall;
    cudaGetSymbolAddress((void**)&xh_m,  g_xh_m);
    cudaGetSymbolAddress((void**)&xh_c,  g_xh_c);
    cudaGetSymbolAddress((void**)&emb,   g_emb);
    cudaGetSymbolAddress((void**)&eg,    g_eg);
    cudaGetSymbolAddress((void**)&gates, g_gates);
    cudaGetSymbolAddress((void**)&hb,    g_h);
    cudaGetSymbolAddress((void**)&cb,    g_c);
    cudaGetSymbolAddress((void**)&ctxb,  g_ctx);
    cudaGetSymbolAddress((void**)&alb,   g_alpha);
    cudaGetSymbolAddress((void**)&sm,    g_sm);
    cudaGetSymbolAddress((void**)&sc,    g_sc);
    cudaGetSymbolAddress((void**)&p,     g_p);
    cudaGetSymbolAddress((void**)&uu,    g_u);
    cudaGetSymbolAddress((void**)&beta,  g_beta);
    cudaGetSymbolAddress((void**)&scall, g_scall);

    /* init recurrent state (buffer 0) */
    init_state<<<(B_*H_ + 255)/256, 256>>>(hb, cb, ctxb, alb);

    /* gather teacher-forced embeddings */
    gather_emb<<<U_*B_, 128>>>(emb_tab, label, emb);

    /* xh_m = x @ Wh_m^T ; xh_c = x @ Wh_c^T   (out[tb*E + e]) */
    sgemm_tn<<<dim3((T_*B_)/BN, (E_+BM-1)/BM), 256>>>(Wh_m, E_, x, E_, nullptr,
            xh_m, 1, E_, E_, T_*B_, E_);
    sgemm_tn<<<dim3((T_*B_)/BN, (E_+BM-1)/BM), 256>>>(Wh_c, E_, x, E_, nullptr,
            xh_c, 1, E_, E_, T_*B_, E_);

    /* eg[ub, j] = emb[ub] @ W_ih[:, :E]^T + b_lstm  (out[ub*4H + j]) */
    sgemm_tn<<<dim3((U_*B_)/BN, G4H/BM), 256>>>(W_ih, 2*E_, emb, E_, b_lstm,
            eg, 1, G4H, G4H, U_*B_, E_);

    /* lm output: out_lm[n*768 + ub] = emb[ub] @ W_lm[n]^T */
    sgemm_tn<<<dim3((U_*B_)/BN, (N_+BM-1)/BM), 256>>>(W_lm, E_, emb, E_, nullptr,
            out_lm, U_*B_, 1, N_, U_*B_, E_);

    for (int u = 0; u < U_; u++) {
        int in = u & 1, out = in ^ 1;
        const float* h_in   = hb   + (size_t)in  * B_*H_;
        float*       h_out  = hb   + (size_t)out * B_*H_;
        const float* c_in   = cb   + (size_t)in  * B_*H_;
        float*       c_out  = cb   + (size_t)out * B_*H_;
        const float* ctx_in = ctxb + (size_t)in  * B_*E_;
        float*       ctx_out= ctxb + (size_t)out * B_*E_;
        const float* al_in  = alb  + (size_t)in  * T_*B_;
        float*       al_out = alb  + (size_t)out * T_*B_;
        float*       sc_u   = scall + (size_t)u * B_ * 2*E_;
        const float* eg_u   = eg    + (size_t)u * B_ * G4H;

        /* gates = eg_u + ctx @ W_ih[:,E:]^T */
        gemv16<<<G4H/8, 256>>>(ctx_in, E_, E_, W_ih + E_, 2*E_,
                               eg_u, G4H, gates, G4H, G4H);
        /* gates += h @ W_hh^T */
        gemv16<<<G4H/8, 256>>>(h_in, H_, H_, W_hh, H_,
                               gates, G4H, gates, G4H, G4H);
        /* LSTM cell */
        lstm_pointwise<<<(B_*H_)/256, 256>>>(gates, c_in, c_out, h_out);
        /* s = h_new @ W_proj^T  -> scall[u][:, 0:E] */
        gemv16<<<E_/8, 256>>>(h_out, H_, H_, W_proj, H_,
                              nullptr, 0, sc_u, 2*E_, E_);
        /* sm = s @ Ws_m^T ; sc = s @ Ws_c^T */
        gemv16<<<E_/8, 256>>>(sc_u, 2*E_, E_, Ws_m, E_, nullptr, 0, sm, E_, E_);
        gemv16<<<E_/8, 256>>>(sc_u, 2*E_, E_, Ws_c, E_, nullptr, 0, sc, E_, E_);
        /* energies -> p, u */
        energies<<<(T_*B_)/8, 256>>>(sm, sc, xh_m, xh_c, v_m, v_c, r_m, att_mask, p, uu);
        /* alpha recursion + beta */
        scanstep<<<B_, T_>>>(p, uu, al_in, att_mask, al_out, beta);
        /* ctx_new -> ctx_out and scall[u][:, E:2E] */
        ctx_update<<<B_, E_>>>(beta, x, ctx_out, sc_u);
    }

    /* am output: out_am[n*768 + ub] = [s;ctx] @ W_am[n]^T */
    sgemm_tn<<<dim3((U_*B_)/BN, (N_+BM-1)/BM), 256>>>(W_am, 2*E_, scall, 2*E_, nullptr,
            out_am, U_*B_, 1, N_, U_*B_, 2*E_);
}